// round 10
// baseline (speedup 1.0000x reference)
#include <cuda_runtime.h>
#include <cuda_fp16.h>
#include <math.h>

#define FEAT 32
#define NA 64
#define NE 32
#define NL 33           // elevation levels L = 0..NE ; quad(L) = levels (L, L+1) incl. poles
#define WARPS 4
#define BLK 128

// Quad table: for azimuth edge al (columns al, al+1 mod NA) and level q:
// g_quad[2*((al*NL+q)*32 + f)] = left pair {v[L],v[L+1]}, [..+1] = right pair. 8B per feature.
// One (al,q) column = 32 * 8B = 256B.
__device__ __half2 g_quad[NA * NL * FEAT * 2];
__device__ float g_ticks_az[NA];
__device__ float g_ticks_el[NE];
__device__ float g_consts[4];  // inv_so_az, inv_so_el, omega_az, omega_el

__global__ void prep_kernel(const float* __restrict__ grid,
                            const float* __restrict__ poles) {
    int idx = blockIdx.x * blockDim.x + threadIdx.x;
    if (idx == 0) {
        double oaz = 2.0 * M_PI / (double)NA;
        double oel = M_PI / (double)(NE + 1);
        g_consts[0] = (float)(1.0 / sin(oaz));
        g_consts[1] = (float)(1.0 / sin(oel));
        g_consts[2] = (float)oaz;
        g_consts[3] = (float)oel;
    }
    if (idx < NA)
        g_ticks_az[idx] = (float)((double)idx * (2.0 * M_PI / (double)NA) - M_PI);
    if (idx < NE)
        g_ticks_el[idx] = (float)((double)(idx + 1) * (M_PI / (double)(NE + 1)) - M_PI / 2.0);
    if (idx < NA * NL * FEAT) {
        int f = idx & 31;
        int c = idx >> 5;
        int q = c % NL;
        int al = c / NL;
        int ar = (al + 1) & (NA - 1);
        float xl = (q == 0)  ? poles[2 * f]     : grid[(((f << 6) + al) << 5) + (q - 1)];
        float yl = (q == NE) ? poles[2 * f + 1] : grid[(((f << 6) + al) << 5) + q];
        float xr = (q == 0)  ? poles[2 * f]     : grid[(((f << 6) + ar) << 5) + (q - 1)];
        float yr = (q == NE) ? poles[2 * f + 1] : grid[(((f << 6) + ar) << 5) + q];
        g_quad[2 * idx]     = __floats2half2_rn(xl, yl);
        g_quad[2 * idx + 1] = __floats2half2_rn(xr, yr);
    }
}

__global__ void __launch_bounds__(BLK, 8)
interp_kernel(const float* __restrict__ pts,
              float* __restrict__ out, int n) {
    __shared__ float  s_ta[NA];
    __shared__ float  s_te[NE];
    __shared__ float  s_c[4];
    __shared__ float4 s_cf[WARPS][32];        // 4 bilinear coeffs (fp32)
    __shared__ float  s_tile[WARPS][32][36];  // point-major [p][f], stride 36

    const int t    = threadIdx.x;
    const int warp = t >> 5;
    const int lane = t & 31;

    if (t < NA) s_ta[t] = g_ticks_az[t];
    if (t < NE) s_te[t] = g_ticks_el[t];
    if (t < 4)  s_c[t]  = g_consts[t];
    __syncthreads();

    const int base = blockIdx.x * BLK + warp * 32;

    // ---------- Phase 1: per-lane point -> 4 coeffs (smem) + offset (reg) ----
    unsigned my_off;
    {
        int ip = base + lane;
        int ic = min(ip, n - 1);
        float az = pts[ic];
        float el = pts[n + ic];

        const float inv_so_az = s_c[0];
        const float inv_so_el = s_c[1];
        const float omega_az  = s_c[2];
        const float omega_el  = s_c[3];

        // azimuth searchsorted(side='left')
        int r = (int)((az + 3.14159274101257324f) / omega_az);
        r = min(max(r, 0), NA);
        while (r < NA && s_ta[r] < az) ++r;
        while (r > 0 && s_ta[r - 1] >= az) --r;
        int al = (r - 1 < 0) ? (NA - 1) : (r - 1);   // ar == (al+1) mod NA always
        float theta_a = az - s_ta[al];
        float w1a = __sinf(omega_az - theta_a) * inv_so_az;
        float w2a = __sinf(theta_a) * inv_so_az;

        // elevation searchsorted -> level q in [0, NE]
        int q = (int)((el + 1.57079637050628662f) / omega_el);
        q = min(max(q, 0), NE);
        while (q < NE && s_te[q] < el) ++q;
        while (q > 0 && s_te[q - 1] >= el) --q;
        bool south = (q == 0);
        bool north = (q == NE);
        float bse = south ? -1.57079632679489662f : s_te[q - 1];
        float theta_e = el - bse;
        float w1e = __sinf(omega_el - theta_e) * inv_so_el;
        float w2e = __sinf(theta_e) * inv_so_el;

        // pole rows appear in BOTH azimuth columns -> renormalize that weight
        float s  = w1a + w2a;
        float wx = south ? __fdividef(w1e, s) : w1e;
        float wy = north ? __fdividef(w2e, s) : w2e;

        s_cf[warp][lane] = make_float4(wx * w1a, wy * w1a, wx * w2a, wy * w2a);
        my_off = (unsigned)(al * NL + q) << 8;   // byte offset of 256B column
    }
    __syncwarp();

    // ---------- Phase 2: 4 points / iteration; lane covers 4 features -------
    // lane = (pi = lane>>3, fq = lane&7): point 4i+pi, features 4fq..4fq+3.
    const char* __restrict__ gq = (const char*)g_quad;
    const int pi = lane >> 3;
    const int fq = lane & 7;

#pragma unroll 4
    for (int i = 0; i < 8; ++i) {
        int p = 4 * i + pi;
        unsigned off = __shfl_sync(0xffffffffu, my_off, p);
        float4 cf = s_cf[warp][p];                 // 4 distinct 16B addrs: 1 wf
        const char* cp = gq + off + 32 * fq;
        uint4 qa = *(const uint4*)(cp);            // features 4fq, 4fq+1
        uint4 qb = *(const uint4*)(cp + 16);       // features 4fq+2, 4fq+3
        float2 l0 = __half22float2(*(const __half2*)&qa.x);
        float2 r0 = __half22float2(*(const __half2*)&qa.y);
        float2 l1 = __half22float2(*(const __half2*)&qa.z);
        float2 r1 = __half22float2(*(const __half2*)&qa.w);
        float2 l2 = __half22float2(*(const __half2*)&qb.x);
        float2 r2 = __half22float2(*(const __half2*)&qb.y);
        float2 l3 = __half22float2(*(const __half2*)&qb.z);
        float2 r3 = __half22float2(*(const __half2*)&qb.w);
        float4 res;
        res.x = fmaf(cf.w, r0.y, fmaf(cf.z, r0.x, fmaf(cf.y, l0.y, cf.x * l0.x)));
        res.y = fmaf(cf.w, r1.y, fmaf(cf.z, r1.x, fmaf(cf.y, l1.y, cf.x * l1.x)));
        res.z = fmaf(cf.w, r2.y, fmaf(cf.z, r2.x, fmaf(cf.y, l2.y, cf.x * l2.x)));
        res.w = fmaf(cf.w, r3.y, fmaf(cf.z, r3.x, fmaf(cf.y, l3.y, cf.x * l3.x)));
        // STS.128 at byte 144p+16fq: aligned; quarter-warp banks (p+fq)%8 distinct
        *(float4*)&s_tile[warp][p][4 * fq] = res;
    }
    __syncwarp();

    // ---------- Phase 3: per-lane LDS.128 (aligned, conflict-free) + STG ----
    int ip = base + lane;
    if (ip < n) {
        float* o = out + ip;
        const size_t sn = (size_t)n;
#pragma unroll
        for (int j = 0; j < 8; ++j) {
            float4 v = *(const float4*)&s_tile[warp][lane][4 * j];
            o[0] = v.x; o += sn;
            o[0] = v.y; o += sn;
            o[0] = v.z; o += sn;
            o[0] = v.w; o += sn;
        }
    }
}

extern "C" void kernel_launch(void* const* d_in, const int* in_sizes, int n_in,
                              void* d_out, int out_size) {
    const float* pts   = (const float*)d_in[0];  // (2, N)
    const float* grid  = (const float*)d_in[1];  // (32, 64, 32)
    const float* poles = (const float*)d_in[2];  // (32, 2)
    float* out = (float*)d_out;                  // (32, N)
    int n = in_sizes[0] / 2;

    prep_kernel<<<(NA * NL * FEAT + 255) / 256, 256>>>(grid, poles);
    interp_kernel<<<(n + BLK - 1) / BLK, BLK>>>(pts, out, n);
}

// round 11
// speedup vs baseline: 1.0862x; 1.0862x over previous
#include <cuda_runtime.h>
#include <cuda_fp16.h>
#include <math.h>

#define FEAT 32
#define NA 64
#define NE 32
#define NL 33           // elevation levels L = 0..NE ; quad(L) = levels (L, L+1) incl. poles
#define WARPS 4
#define BLK 128

// Quad table: for azimuth edge al (columns al, al+1 mod NA) and level q:
// g_quad[2*((al*NL+q)*32 + f)] = left pair {v[L],v[L+1]}, [..+1] = right pair. 8B per feature.
// One (al,q) column = 32 * 8B = 256B (256B-aligned).
__device__ __half2 g_quad[NA * NL * FEAT * 2];
__device__ float g_ticks_az[NA];
__device__ float g_ticks_el[NE];
__device__ float g_consts[4];  // inv_so_az, inv_so_el, omega_az, omega_el

__global__ void prep_kernel(const float* __restrict__ grid,
                            const float* __restrict__ poles) {
    int idx = blockIdx.x * blockDim.x + threadIdx.x;
    if (idx == 0) {
        double oaz = 2.0 * M_PI / (double)NA;
        double oel = M_PI / (double)(NE + 1);
        g_consts[0] = (float)(1.0 / sin(oaz));
        g_consts[1] = (float)(1.0 / sin(oel));
        g_consts[2] = (float)oaz;
        g_consts[3] = (float)oel;
    }
    if (idx < NA)
        g_ticks_az[idx] = (float)((double)idx * (2.0 * M_PI / (double)NA) - M_PI);
    if (idx < NE)
        g_ticks_el[idx] = (float)((double)(idx + 1) * (M_PI / (double)(NE + 1)) - M_PI / 2.0);
    if (idx < NA * NL * FEAT) {
        int f = idx & 31;
        int c = idx >> 5;
        int q = c % NL;
        int al = c / NL;
        int ar = (al + 1) & (NA - 1);
        float xl = (q == 0)  ? poles[2 * f]     : grid[(((f << 6) + al) << 5) + (q - 1)];
        float yl = (q == NE) ? poles[2 * f + 1] : grid[(((f << 6) + al) << 5) + q];
        float xr = (q == 0)  ? poles[2 * f]     : grid[(((f << 6) + ar) << 5) + (q - 1)];
        float yr = (q == NE) ? poles[2 * f + 1] : grid[(((f << 6) + ar) << 5) + q];
        g_quad[2 * idx]     = __floats2half2_rn(xl, yl);
        g_quad[2 * idx + 1] = __floats2half2_rn(xr, yr);
    }
}

__global__ void __launch_bounds__(BLK, 8)
interp_kernel(const float* __restrict__ pts,
              float* __restrict__ out, int n) {
    __shared__ float  s_ta[NA];
    __shared__ float  s_te[NE];
    __shared__ float  s_c[4];
    __shared__ float4 s_cf[WARPS][32];        // 4 bilinear coeffs (fp32)
    __shared__ float  s_tile[WARPS][32][36];  // point-major [p][slot], stride 36

    const int t    = threadIdx.x;
    const int warp = t >> 5;
    const int lane = t & 31;

    if (t < NA) s_ta[t] = g_ticks_az[t];
    if (t < NE) s_te[t] = g_ticks_el[t];
    if (t < 4)  s_c[t]  = g_consts[t];
    __syncthreads();

    const int base = blockIdx.x * BLK + warp * 32;

    // ---------- Phase 1: per-lane point -> 4 coeffs (smem) + offset (reg) ----
    unsigned my_off;
    {
        int ip = base + lane;
        int ic = min(ip, n - 1);
        float az = pts[ic];
        float el = pts[n + ic];

        const float inv_so_az = s_c[0];
        const float inv_so_el = s_c[1];
        const float omega_az  = s_c[2];
        const float omega_el  = s_c[3];

        // azimuth searchsorted(side='left')
        int r = (int)((az + 3.14159274101257324f) / omega_az);
        r = min(max(r, 0), NA);
        while (r < NA && s_ta[r] < az) ++r;
        while (r > 0 && s_ta[r - 1] >= az) --r;
        int al = (r - 1 < 0) ? (NA - 1) : (r - 1);   // ar == (al+1) mod NA always
        float theta_a = az - s_ta[al];
        float w1a = __sinf(omega_az - theta_a) * inv_so_az;
        float w2a = __sinf(theta_a) * inv_so_az;

        // elevation searchsorted -> level q in [0, NE]
        int q = (int)((el + 1.57079637050628662f) / omega_el);
        q = min(max(q, 0), NE);
        while (q < NE && s_te[q] < el) ++q;
        while (q > 0 && s_te[q - 1] >= el) --q;
        bool south = (q == 0);
        bool north = (q == NE);
        float bse = south ? -1.57079632679489662f : s_te[q - 1];
        float theta_e = el - bse;
        float w1e = __sinf(omega_el - theta_e) * inv_so_el;
        float w2e = __sinf(theta_e) * inv_so_el;

        // pole rows appear in BOTH azimuth columns -> renormalize that weight
        float s  = w1a + w2a;
        float wx = south ? __fdividef(w1e, s) : w1e;
        float wy = north ? __fdividef(w2e, s) : w2e;

        s_cf[warp][lane] = make_float4(wx * w1a, wy * w1a, wx * w2a, wy * w2a);
        my_off = (unsigned)(al * NL + q) << 8;   // byte offset of 256B column
    }
    __syncwarp();

    // ---------- Phase 2: 4 points / iteration, line-local gathers -----------
    // lane = (pi = lane>>3, fq = lane&7): point 4i+pi.
    // qa = column bytes [16fq, 16fq+16)   -> features 2fq, 2fq+1   (line 0)
    // qb = column bytes [128+16fq, ..+16) -> features 16+2fq, 17+2fq (line 1)
    // Tile slot 4fq..4fq+3 of point p holds features {2fq, 2fq+1, 16+2fq, 17+2fq}.
    const char* __restrict__ gq = (const char*)g_quad;
    const int pi = lane >> 3;
    const int fq = lane & 7;

#pragma unroll 4
    for (int i = 0; i < 8; ++i) {
        int p = 4 * i + pi;
        unsigned off = __shfl_sync(0xffffffffu, my_off, p);
        float4 cf = s_cf[warp][p];                 // 4 distinct 16B addrs: 1 wf
        const char* cp = gq + off + 16 * fq;
        uint4 qa = *(const uint4*)(cp);            // features 2fq, 2fq+1
        uint4 qb = *(const uint4*)(cp + 128);      // features 16+2fq, 17+2fq
        float2 l0 = __half22float2(*(const __half2*)&qa.x);
        float2 r0 = __half22float2(*(const __half2*)&qa.y);
        float2 l1 = __half22float2(*(const __half2*)&qa.z);
        float2 r1 = __half22float2(*(const __half2*)&qa.w);
        float2 l2 = __half22float2(*(const __half2*)&qb.x);
        float2 r2 = __half22float2(*(const __half2*)&qb.y);
        float2 l3 = __half22float2(*(const __half2*)&qb.z);
        float2 r3 = __half22float2(*(const __half2*)&qb.w);
        float4 res;
        res.x = fmaf(cf.w, r0.y, fmaf(cf.z, r0.x, fmaf(cf.y, l0.y, cf.x * l0.x)));
        res.y = fmaf(cf.w, r1.y, fmaf(cf.z, r1.x, fmaf(cf.y, l1.y, cf.x * l1.x)));
        res.z = fmaf(cf.w, r2.y, fmaf(cf.z, r2.x, fmaf(cf.y, l2.y, cf.x * l2.x)));
        res.w = fmaf(cf.w, r3.y, fmaf(cf.z, r3.x, fmaf(cf.y, l3.y, cf.x * l3.x)));
        // STS.128 at byte 144p+16fq: aligned; phase banks (4p+4fq)%32 distinct
        *(float4*)&s_tile[warp][p][4 * fq] = res;
    }
    __syncwarp();

    // ---------- Phase 3: per-lane LDS.128 + STG, un-permuting features ------
    int ip = base + lane;
    if (ip < n) {
        const size_t sn = (size_t)n;
        float* o_lo = out + ip;                  // rows 2j, 2j+1
        float* o_hi = out + 16 * sn + ip;        // rows 16+2j, 17+2j
#pragma unroll
        for (int j = 0; j < 8; ++j) {
            float4 v = *(const float4*)&s_tile[warp][lane][4 * j];
            o_lo[(size_t)(2 * j)     * sn] = v.x;
            o_lo[(size_t)(2 * j + 1) * sn] = v.y;
            o_hi[(size_t)(2 * j)     * sn] = v.z;
            o_hi[(size_t)(2 * j + 1) * sn] = v.w;
        }
    }
}

extern "C" void kernel_launch(void* const* d_in, const int* in_sizes, int n_in,
                              void* d_out, int out_size) {
    const float* pts   = (const float*)d_in[0];  // (2, N)
    const float* grid  = (const float*)d_in[1];  // (32, 64, 32)
    const float* poles = (const float*)d_in[2];  // (32, 2)
    float* out = (float*)d_out;                  // (32, N)
    int n = in_sizes[0] / 2;

    prep_kernel<<<(NA * NL * FEAT + 255) / 256, 256>>>(grid, poles);
    interp_kernel<<<(n + BLK - 1) / BLK, BLK>>>(pts, out, n);
}

// round 12
// speedup vs baseline: 1.1560x; 1.0642x over previous
#include <cuda_runtime.h>
#include <cuda_fp16.h>
#include <math.h>

#define FEAT 32
#define NA 64
#define NE 32
#define NL 33           // elevation levels L = 0..NE ; quad(L) = levels (L, L+1) incl. poles
#define WARPS 4
#define BLK 128

// Quad table: for azimuth edge al (columns al, al+1 mod NA) and level q:
// g_quad[2*((al*NL+q)*32 + f)] = left pair {v[L],v[L+1]}, [..+1] = right pair. 8B per feature.
// One (al,q) column = 32 * 8B = 256B (256B-aligned).
__device__ __half2 g_quad[NA * NL * FEAT * 2];
__device__ float g_ticks_az[NA];
__device__ float g_ticks_el[NE];
__device__ float g_consts[4];  // inv_so_az, inv_so_el, omega_az, omega_el

__global__ void prep_kernel(const float* __restrict__ grid,
                            const float* __restrict__ poles) {
    int idx = blockIdx.x * blockDim.x + threadIdx.x;
    if (idx == 0) {
        double oaz = 2.0 * M_PI / (double)NA;
        double oel = M_PI / (double)(NE + 1);
        g_consts[0] = (float)(1.0 / sin(oaz));
        g_consts[1] = (float)(1.0 / sin(oel));
        g_consts[2] = (float)oaz;
        g_consts[3] = (float)oel;
    }
    if (idx < NA)
        g_ticks_az[idx] = (float)((double)idx * (2.0 * M_PI / (double)NA) - M_PI);
    if (idx < NE)
        g_ticks_el[idx] = (float)((double)(idx + 1) * (M_PI / (double)(NE + 1)) - M_PI / 2.0);
    if (idx < NA * NL * FEAT) {
        int f = idx & 31;
        int c = idx >> 5;
        int q = c % NL;
        int al = c / NL;
        int ar = (al + 1) & (NA - 1);
        float xl = (q == 0)  ? poles[2 * f]     : grid[(((f << 6) + al) << 5) + (q - 1)];
        float yl = (q == NE) ? poles[2 * f + 1] : grid[(((f << 6) + al) << 5) + q];
        float xr = (q == 0)  ? poles[2 * f]     : grid[(((f << 6) + ar) << 5) + (q - 1)];
        float yr = (q == NE) ? poles[2 * f + 1] : grid[(((f << 6) + ar) << 5) + q];
        g_quad[2 * idx]     = __floats2half2_rn(xl, yl);
        g_quad[2 * idx + 1] = __floats2half2_rn(xr, yr);
    }
}

__global__ void __launch_bounds__(BLK, 8)
interp_kernel(const float* __restrict__ pts,
              float* __restrict__ out, int n) {
    __shared__ float  s_ta[NA];
    __shared__ float  s_te[NE];
    __shared__ float  s_c[4];
    __shared__ float4 s_cf[WARPS][32];        // 4 bilinear coeffs (fp32)
    // fp16 transpose tile: row(p) = 8*(p&3) + (p>>2); 8 uint2 slots + 1 pad.
    // slot s (logical) holds half2 pairs: .x = feats (2s,2s+1), .y = (16+2s,17+2s),
    // stored at physical slot s ^ ((p>>1)&1).
    __shared__ uint2  s_tile[WARPS][32][9];

    const int t    = threadIdx.x;
    const int warp = t >> 5;
    const int lane = t & 31;

    if (t < NA) s_ta[t] = g_ticks_az[t];
    if (t < NE) s_te[t] = g_ticks_el[t];
    if (t < 4)  s_c[t]  = g_consts[t];
    __syncthreads();

    const int base = blockIdx.x * BLK + warp * 32;

    // ---------- Phase 1: per-lane point -> 4 coeffs (smem) + offset (reg) ----
    unsigned my_off;
    {
        int ip = base + lane;
        int ic = min(ip, n - 1);
        float az = pts[ic];
        float el = pts[n + ic];

        const float inv_so_az = s_c[0];
        const float inv_so_el = s_c[1];
        const float omega_az  = s_c[2];
        const float omega_el  = s_c[3];

        // azimuth searchsorted(side='left')
        int r = (int)((az + 3.14159274101257324f) / omega_az);
        r = min(max(r, 0), NA);
        while (r < NA && s_ta[r] < az) ++r;
        while (r > 0 && s_ta[r - 1] >= az) --r;
        int al = (r - 1 < 0) ? (NA - 1) : (r - 1);   // ar == (al+1) mod NA always
        float theta_a = az - s_ta[al];
        float w1a = __sinf(omega_az - theta_a) * inv_so_az;
        float w2a = __sinf(theta_a) * inv_so_az;

        // elevation searchsorted -> level q in [0, NE]
        int q = (int)((el + 1.57079637050628662f) / omega_el);
        q = min(max(q, 0), NE);
        while (q < NE && s_te[q] < el) ++q;
        while (q > 0 && s_te[q - 1] >= el) --q;
        bool south = (q == 0);
        bool north = (q == NE);
        float bse = south ? -1.57079632679489662f : s_te[q - 1];
        float theta_e = el - bse;
        float w1e = __sinf(omega_el - theta_e) * inv_so_el;
        float w2e = __sinf(theta_e) * inv_so_el;

        // pole rows appear in BOTH azimuth columns -> renormalize that weight
        float s  = w1a + w2a;
        float wx = south ? __fdividef(w1e, s) : w1e;
        float wy = north ? __fdividef(w2e, s) : w2e;

        s_cf[warp][lane] = make_float4(wx * w1a, wy * w1a, wx * w2a, wy * w2a);
        my_off = (unsigned)(al * NL + q) << 8;   // byte offset of 256B column
    }
    __syncwarp();

    // ---------- Phase 2: 4 points / iteration, line-local gathers -----------
    // lane = (pi = lane>>3, fq = lane&7): point p = 4i+pi.
    // qa -> features 2fq, 2fq+1 (line 0 of column); qb -> 16+2fq, 17+2fq (line 1).
    const char* __restrict__ gq = (const char*)g_quad;
    const int pi = lane >> 3;
    const int fq = lane & 7;
    const int sx = (pi >> 1) & 1;      // chunk XOR for this writer's points
    const int sl = fq ^ sx;            // physical uint2 slot

#pragma unroll 4
    for (int i = 0; i < 8; ++i) {
        int p = 4 * i + pi;
        unsigned off = __shfl_sync(0xffffffffu, my_off, p);
        float4 cf = s_cf[warp][p];                 // 4 distinct 16B addrs: 1 wf
        const char* cp = gq + off + 16 * fq;
        uint4 qa = *(const uint4*)(cp);            // features 2fq, 2fq+1
        uint4 qb = *(const uint4*)(cp + 128);      // features 16+2fq, 17+2fq
        float2 l0 = __half22float2(*(const __half2*)&qa.x);
        float2 r0 = __half22float2(*(const __half2*)&qa.y);
        float2 l1 = __half22float2(*(const __half2*)&qa.z);
        float2 r1 = __half22float2(*(const __half2*)&qa.w);
        float2 l2 = __half22float2(*(const __half2*)&qb.x);
        float2 r2 = __half22float2(*(const __half2*)&qb.y);
        float2 l3 = __half22float2(*(const __half2*)&qb.z);
        float2 r3 = __half22float2(*(const __half2*)&qb.w);
        float res0 = fmaf(cf.w, r0.y, fmaf(cf.z, r0.x, fmaf(cf.y, l0.y, cf.x * l0.x)));
        float res1 = fmaf(cf.w, r1.y, fmaf(cf.z, r1.x, fmaf(cf.y, l1.y, cf.x * l1.x)));
        float res2 = fmaf(cf.w, r2.y, fmaf(cf.z, r2.x, fmaf(cf.y, l2.y, cf.x * l2.x)));
        float res3 = fmaf(cf.w, r3.y, fmaf(cf.z, r3.x, fmaf(cf.y, l3.y, cf.x * l3.x)));
        __half2 ha = __floats2half2_rn(res0, res1);   // feats 2fq, 2fq+1
        __half2 hb = __floats2half2_rn(res2, res3);   // feats 16+2fq, 17+2fq
        int row = 8 * pi + i;                          // row(p) = 8*(p&3) + (p>>2)
        // STS.64: phase banks verified all-distinct (pi-groups 16 apart, XOR splits pairs)
        s_tile[warp][row][sl] = make_uint2(*(unsigned*)&ha, *(unsigned*)&hb);
    }
    __syncwarp();

    // ---------- Phase 3: 8x LDS.64 (conflict-free) + unpack + coalesced STG -
    int ip = base + lane;
    if (ip < n) {
        const int row = 8 * (lane & 3) + (lane >> 2);
        const int x   = (lane >> 1) & 1;
        const size_t sn = (size_t)n;
        float* o = out + ip;
#pragma unroll
        for (int m = 0; m < 8; ++m) {
            uint2 v = s_tile[warp][row][m ^ x];
            float2 a = __half22float2(*(const __half2*)&v.x);  // feats 2m, 2m+1
            float2 b = __half22float2(*(const __half2*)&v.y);  // feats 16+2m, 17+2m
            o[(size_t)(2 * m)      * sn] = a.x;
            o[(size_t)(2 * m + 1)  * sn] = a.y;
            o[(size_t)(16 + 2 * m) * sn] = b.x;
            o[(size_t)(17 + 2 * m) * sn] = b.y;
        }
    }
}

extern "C" void kernel_launch(void* const* d_in, const int* in_sizes, int n_in,
                              void* d_out, int out_size) {
    const float* pts   = (const float*)d_in[0];  // (2, N)
    const float* grid  = (const float*)d_in[1];  // (32, 64, 32)
    const float* poles = (const float*)d_in[2];  // (32, 2)
    float* out = (float*)d_out;                  // (32, N)
    int n = in_sizes[0] / 2;

    prep_kernel<<<(NA * NL * FEAT + 255) / 256, 256>>>(grid, poles);
    interp_kernel<<<(n + BLK - 1) / BLK, BLK>>>(pts, out, n);
}

// round 13
// speedup vs baseline: 1.3018x; 1.1261x over previous
#include <cuda_runtime.h>
#include <cuda_fp16.h>
#include <math.h>

#define FEAT 32
#define NA 64
#define NE 32
#define NL 33           // elevation levels L = 0..NE ; quad(L) = levels (L, L+1) incl. poles
#define WARPS 4
#define BLK 128

// Quad table: for azimuth edge al (columns al, al+1 mod NA) and level q:
// g_quad[2*((al*NL+q)*32 + f)] = left pair {v[L],v[L+1]}, [..+1] = right pair. 8B per feature.
// One (al,q) column = 32 * 8B = 256B (256B-aligned).
__device__ __half2 g_quad[NA * NL * FEAT * 2];
__device__ float g_consts[4];  // inv_so_az, inv_so_el, omega_az, omega_el

__global__ void prep_kernel(const float* __restrict__ grid,
                            const float* __restrict__ poles) {
    int idx = blockIdx.x * blockDim.x + threadIdx.x;
    if (idx == 0) {
        double oaz = 2.0 * M_PI / (double)NA;
        double oel = M_PI / (double)(NE + 1);
        g_consts[0] = (float)(1.0 / sin(oaz));
        g_consts[1] = (float)(1.0 / sin(oel));
        g_consts[2] = (float)oaz;
        g_consts[3] = (float)oel;
    }
    if (idx < NA * NL * FEAT) {
        int f = idx & 31;
        int c = idx >> 5;
        int q = c % NL;
        int al = c / NL;
        int ar = (al + 1) & (NA - 1);
        float xl = (q == 0)  ? poles[2 * f]     : grid[(((f << 6) + al) << 5) + (q - 1)];
        float yl = (q == NE) ? poles[2 * f + 1] : grid[(((f << 6) + al) << 5) + q];
        float xr = (q == 0)  ? poles[2 * f]     : grid[(((f << 6) + ar) << 5) + (q - 1)];
        float yr = (q == NE) ? poles[2 * f + 1] : grid[(((f << 6) + ar) << 5) + q];
        g_quad[2 * idx]     = __floats2half2_rn(xl, yl);
        g_quad[2 * idx + 1] = __floats2half2_rn(xr, yr);
    }
}

__global__ void __launch_bounds__(BLK, 8)
interp_kernel(const float* __restrict__ pts,
              float* __restrict__ out, int n) {
    __shared__ float4 s_cf[WARPS][32];        // 4 bilinear coeffs (fp32)
    // fp16 transpose tile: row(p) = 8*(p&3) + (p>>2); 8 uint2 slots + 1 pad.
    // slot s (logical) holds half2 pairs: .x = feats (2s,2s+1), .y = (16+2s,17+2s),
    // stored at physical slot s ^ ((p>>1)&1).
    __shared__ uint2  s_tile[WARPS][32][9];

    const int t    = threadIdx.x;
    const int warp = t >> 5;
    const int lane = t & 31;

    const int base = blockIdx.x * BLK + warp * 32;

    // ---------- Phase 1: analytic binning (no tick tables, no fixup loops) --
    // slerp is continuous at every tick, so approximate binning is exact to
    // ~1e-7 in the result; base_el = q*omega_el - pi/2 holds for all branches.
    unsigned my_off;
    {
        const float4 c0 = *(const float4*)g_consts;  // inv_so_az, inv_so_el, w_az, w_el
        const float inv_w_az = 10.185916357881302f;  // NA / (2 pi)   (binning only)
        const float inv_w_el = 10.504226244065093f;  // (NE+1) / pi   (binning only)

        int ip = base + lane;
        int ic = min(ip, n - 1);
        float az = pts[ic];
        float el = pts[n + ic];

        float u = az + 3.14159274101257324f;         // [0, 2pi)
        int al = __float2int_rd(u * inv_w_az);
        al = min(max(al, 0), NA - 1);
        float theta_a = fmaf(-(float)al, c0.z, u);
        float w1a = __sinf(c0.z - theta_a) * c0.x;
        float w2a = __sinf(theta_a) * c0.x;

        float v = el + 1.57079637050628662f;         // [0, pi]
        int q = __float2int_rd(v * inv_w_el);
        q = min(max(q, 0), NE);
        float theta_e = fmaf(-(float)q, c0.w, v);
        float w1e = __sinf(c0.w - theta_e) * c0.y;
        float w2e = __sinf(theta_e) * c0.y;

        // pole rows appear in BOTH azimuth columns -> renormalize that weight
        float s  = w1a + w2a;
        float wx = (q == 0)  ? __fdividef(w1e, s) : w1e;
        float wy = (q == NE) ? __fdividef(w2e, s) : w2e;

        s_cf[warp][lane] = make_float4(wx * w1a, wy * w1a, wx * w2a, wy * w2a);
        my_off = (unsigned)(al * NL + q) << 8;       // byte offset of 256B column
    }
    __syncwarp();

    // ---------- Phase 2: 4 points / iteration, line-local gathers -----------
    // lane = (pi = lane>>3, fq = lane&7): point p = 4i+pi.
    // qa -> features 2fq, 2fq+1 (line 0 of column); qb -> 16+2fq, 17+2fq (line 1).
    const char* __restrict__ gq = (const char*)g_quad;
    const int pi = lane >> 3;
    const int fq = lane & 7;
    const int sx = (pi >> 1) & 1;      // chunk XOR for this writer's points
    const int sl = fq ^ sx;            // physical uint2 slot

#pragma unroll 4
    for (int i = 0; i < 8; ++i) {
        int p = 4 * i + pi;
        unsigned off = __shfl_sync(0xffffffffu, my_off, p);
        float4 cf = s_cf[warp][p];                 // 4 distinct 16B addrs: 1 wf
        const char* cp = gq + off + 16 * fq;
        uint4 qa = *(const uint4*)(cp);            // features 2fq, 2fq+1
        uint4 qb = *(const uint4*)(cp + 128);      // features 16+2fq, 17+2fq
        float2 l0 = __half22float2(*(const __half2*)&qa.x);
        float2 r0 = __half22float2(*(const __half2*)&qa.y);
        float2 l1 = __half22float2(*(const __half2*)&qa.z);
        float2 r1 = __half22float2(*(const __half2*)&qa.w);
        float2 l2 = __half22float2(*(const __half2*)&qb.x);
        float2 r2 = __half22float2(*(const __half2*)&qb.y);
        float2 l3 = __half22float2(*(const __half2*)&qb.z);
        float2 r3 = __half22float2(*(const __half2*)&qb.w);
        float res0 = fmaf(cf.w, r0.y, fmaf(cf.z, r0.x, fmaf(cf.y, l0.y, cf.x * l0.x)));
        float res1 = fmaf(cf.w, r1.y, fmaf(cf.z, r1.x, fmaf(cf.y, l1.y, cf.x * l1.x)));
        float res2 = fmaf(cf.w, r2.y, fmaf(cf.z, r2.x, fmaf(cf.y, l2.y, cf.x * l2.x)));
        float res3 = fmaf(cf.w, r3.y, fmaf(cf.z, r3.x, fmaf(cf.y, l3.y, cf.x * l3.x)));
        __half2 ha = __floats2half2_rn(res0, res1);   // feats 2fq, 2fq+1
        __half2 hb = __floats2half2_rn(res2, res3);   // feats 16+2fq, 17+2fq
        int row = 8 * pi + i;                          // row(p) = 8*(p&3) + (p>>2)
        s_tile[warp][row][sl] = make_uint2(*(unsigned*)&ha, *(unsigned*)&hb);
    }
    __syncwarp();

    // ---------- Phase 3: 8x LDS.64 (conflict-free) + unpack + coalesced STG -
    int ip = base + lane;
    if (ip < n) {
        const int row = 8 * (lane & 3) + (lane >> 2);
        const int x   = (lane >> 1) & 1;
        const size_t sn = (size_t)n;
        float* o = out + ip;
#pragma unroll
        for (int m = 0; m < 8; ++m) {
            uint2 v = s_tile[warp][row][m ^ x];
            float2 a = __half22float2(*(const __half2*)&v.x);  // feats 2m, 2m+1
            float2 b = __half22float2(*(const __half2*)&v.y);  // feats 16+2m, 17+2m
            o[(size_t)(2 * m)      * sn] = a.x;
            o[(size_t)(2 * m + 1)  * sn] = a.y;
            o[(size_t)(16 + 2 * m) * sn] = b.x;
            o[(size_t)(17 + 2 * m) * sn] = b.y;
        }
    }
}

extern "C" void kernel_launch(void* const* d_in, const int* in_sizes, int n_in,
                              void* d_out, int out_size) {
    const float* pts   = (const float*)d_in[0];  // (2, N)
    const float* grid  = (const float*)d_in[1];  // (32, 64, 32)
    const float* poles = (const float*)d_in[2];  // (32, 2)
    float* out = (float*)d_out;                  // (32, N)
    int n = in_sizes[0] / 2;

    prep_kernel<<<(NA * NL * FEAT + 255) / 256, 256>>>(grid, poles);
    interp_kernel<<<(n + BLK - 1) / BLK, BLK>>>(pts, out, n);
}

// round 14
// speedup vs baseline: 1.3099x; 1.0062x over previous
#include <cuda_runtime.h>
#include <cuda_fp16.h>
#include <math.h>

#define FEAT 32
#define NA 64
#define NE 32
#define NL 33           // elevation levels L = 0..NE ; quad(L) = levels (L, L+1) incl. poles
#define WARPS 4
#define BLK 128

// Quad table: for azimuth edge al (columns al, al+1 mod NA) and level q:
// g_quad[2*((al*NL+q)*32 + f)] = left pair {v[L],v[L+1]}, [..+1] = right pair. 8B per feature.
// One (al,q) column = 32 * 8B = 256B (256B-aligned).
__device__ __half2 g_quad[NA * NL * FEAT * 2];
__device__ float g_consts[4];  // inv_so_az, inv_so_el, omega_az, omega_el

__global__ void prep_kernel(const float* __restrict__ grid,
                            const float* __restrict__ poles) {
    int idx = blockIdx.x * blockDim.x + threadIdx.x;
    if (idx == 0) {
        double oaz = 2.0 * M_PI / (double)NA;
        double oel = M_PI / (double)(NE + 1);
        g_consts[0] = (float)(1.0 / sin(oaz));
        g_consts[1] = (float)(1.0 / sin(oel));
        g_consts[2] = (float)oaz;
        g_consts[3] = (float)oel;
    }
    if (idx < NA * NL * FEAT) {
        int f = idx & 31;
        int c = idx >> 5;
        int q = c % NL;
        int al = c / NL;
        int ar = (al + 1) & (NA - 1);
        float xl = (q == 0)  ? poles[2 * f]     : grid[(((f << 6) + al) << 5) + (q - 1)];
        float yl = (q == NE) ? poles[2 * f + 1] : grid[(((f << 6) + al) << 5) + q];
        float xr = (q == 0)  ? poles[2 * f]     : grid[(((f << 6) + ar) << 5) + (q - 1)];
        float yr = (q == NE) ? poles[2 * f + 1] : grid[(((f << 6) + ar) << 5) + q];
        g_quad[2 * idx]     = __floats2half2_rn(xl, yl);
        g_quad[2 * idx + 1] = __floats2half2_rn(xr, yr);
    }
}

__global__ void __launch_bounds__(BLK, 10)
interp_kernel(const float* __restrict__ pts,
              float* __restrict__ out, int n) {
    __shared__ float4 s_cf[WARPS][32];        // 4 bilinear coeffs (fp32)
    // fp16 transpose tile: row(p) = 8*(p&3) + (p>>2); 8 uint2 slots + 1 pad.
    // slot s (logical) holds half2 pairs: .x = feats (2s,2s+1), .y = (16+2s,17+2s),
    // stored at physical slot s ^ ((p>>1)&1).
    __shared__ uint2  s_tile[WARPS][32][9];

    const int t    = threadIdx.x;
    const int warp = t >> 5;
    const int lane = t & 31;

    const int base = blockIdx.x * BLK + warp * 32;

    // ---------- Phase 1: analytic binning (no tick tables, no fixup loops) --
    unsigned my_off;
    {
        const float4 c0 = *(const float4*)g_consts;  // inv_so_az, inv_so_el, w_az, w_el
        const float inv_w_az = 10.185916357881302f;  // NA / (2 pi)   (binning only)
        const float inv_w_el = 10.504226244065093f;  // (NE+1) / pi   (binning only)

        int ip = base + lane;
        int ic = min(ip, n - 1);
        float az = pts[ic];
        float el = pts[n + ic];

        float u = az + 3.14159274101257324f;         // [0, 2pi)
        int al = __float2int_rd(u * inv_w_az);
        al = min(max(al, 0), NA - 1);
        float theta_a = fmaf(-(float)al, c0.z, u);
        float w1a = __sinf(c0.z - theta_a) * c0.x;
        float w2a = __sinf(theta_a) * c0.x;

        float v = el + 1.57079637050628662f;         // [0, pi]
        int q = __float2int_rd(v * inv_w_el);
        q = min(max(q, 0), NE);
        float theta_e = fmaf(-(float)q, c0.w, v);
        float w1e = __sinf(c0.w - theta_e) * c0.y;
        float w2e = __sinf(theta_e) * c0.y;

        // pole rows appear in BOTH azimuth columns -> renormalize that weight
        float s  = w1a + w2a;
        float wx = (q == 0)  ? __fdividef(w1e, s) : w1e;
        float wy = (q == NE) ? __fdividef(w2e, s) : w2e;

        s_cf[warp][lane] = make_float4(wx * w1a, wy * w1a, wx * w2a, wy * w2a);
        my_off = (unsigned)(al * NL + q) << 8;       // byte offset of 256B column
    }
    __syncwarp();

    // ---------- Phase 2: 4 points / iteration, line-local gathers -----------
    // lane = (pi = lane>>3, fq = lane&7): point p = 4i+pi.
    // qa -> features 2fq, 2fq+1 (line 0 of column); qb -> 16+2fq, 17+2fq (line 1).
    const char* __restrict__ gq = (const char*)g_quad;
    const int pi = lane >> 3;
    const int fq = lane & 7;
    const int sx = (pi >> 1) & 1;      // chunk XOR for this writer's points
    const int sl = fq ^ sx;            // physical uint2 slot

#pragma unroll 4
    for (int i = 0; i < 8; ++i) {
        int p = 4 * i + pi;
        unsigned off = __shfl_sync(0xffffffffu, my_off, p);
        float4 cf = s_cf[warp][p];                 // 4 distinct 16B addrs: 1 wf
        const char* cp = gq + off + 16 * fq;
        uint4 qa = *(const uint4*)(cp);            // features 2fq, 2fq+1
        uint4 qb = *(const uint4*)(cp + 128);      // features 16+2fq, 17+2fq

        // compute results sequentially to keep live ranges short
        float2 la = __half22float2(*(const __half2*)&qa.x);
        float2 ra = __half22float2(*(const __half2*)&qa.y);
        float res0 = fmaf(cf.w, ra.y, fmaf(cf.z, ra.x, fmaf(cf.y, la.y, cf.x * la.x)));
        la = __half22float2(*(const __half2*)&qa.z);
        ra = __half22float2(*(const __half2*)&qa.w);
        float res1 = fmaf(cf.w, ra.y, fmaf(cf.z, ra.x, fmaf(cf.y, la.y, cf.x * la.x)));
        __half2 ha = __floats2half2_rn(res0, res1);   // feats 2fq, 2fq+1

        la = __half22float2(*(const __half2*)&qb.x);
        ra = __half22float2(*(const __half2*)&qb.y);
        res0 = fmaf(cf.w, ra.y, fmaf(cf.z, ra.x, fmaf(cf.y, la.y, cf.x * la.x)));
        la = __half22float2(*(const __half2*)&qb.z);
        ra = __half22float2(*(const __half2*)&qb.w);
        res1 = fmaf(cf.w, ra.y, fmaf(cf.z, ra.x, fmaf(cf.y, la.y, cf.x * la.x)));
        __half2 hb = __floats2half2_rn(res0, res1);   // feats 16+2fq, 17+2fq

        int row = 8 * pi + i;                          // row(p) = 8*(p&3) + (p>>2)
        s_tile[warp][row][sl] = make_uint2(*(unsigned*)&ha, *(unsigned*)&hb);
    }
    __syncwarp();

    // ---------- Phase 3: 8x LDS.64 (conflict-free) + unpack + coalesced STG -
    int ip = base + lane;
    if (ip < n) {
        const int row = 8 * (lane & 3) + (lane >> 2);
        const int x   = (lane >> 1) & 1;
        const size_t sn = (size_t)n;
        float* o = out + ip;
#pragma unroll
        for (int m = 0; m < 8; ++m) {
            uint2 v = s_tile[warp][row][m ^ x];
            float2 a = __half22float2(*(const __half2*)&v.x);  // feats 2m, 2m+1
            float2 b = __half22float2(*(const __half2*)&v.y);  // feats 16+2m, 17+2m
            o[(size_t)(2 * m)      * sn] = a.x;
            o[(size_t)(2 * m + 1)  * sn] = a.y;
            o[(size_t)(16 + 2 * m) * sn] = b.x;
            o[(size_t)(17 + 2 * m) * sn] = b.y;
        }
    }
}

extern "C" void kernel_launch(void* const* d_in, const int* in_sizes, int n_in,
                              void* d_out, int out_size) {
    const float* pts   = (const float*)d_in[0];  // (2, N)
    const float* grid  = (const float*)d_in[1];  // (32, 64, 32)
    const float* poles = (const float*)d_in[2];  // (32, 2)
    float* out = (float*)d_out;                  // (32, N)
    int n = in_sizes[0] / 2;

    prep_kernel<<<(NA * NL * FEAT + 255) / 256, 256>>>(grid, poles);
    interp_kernel<<<(n + BLK - 1) / BLK, BLK>>>(pts, out, n);
}